// round 2
// baseline (speedup 1.0000x reference)
#include <cuda_runtime.h>

#define N_NODES 50000
#define N_EDGES 600000
#define D 128

// ---- scratch (device globals: no allocation allowed) ----
__device__ int   g_deg[N_NODES];
__device__ int   g_off[N_NODES + 1];
__device__ int   g_cur[N_NODES];
__device__ float g_inv[N_NODES];
__device__ int   g_csr_src[N_EDGES];
__device__ float g_agg[(size_t)N_NODES * D];
__device__ int   g_is64;

__device__ __forceinline__ int load_idx(const void* p, int e, int is64) {
    if (is64) return (int)((const long long*)p)[e];
    return ((const int*)p)[e];
}

// Kernel 1: zero degree array + detect whether index arrays are int64 or int32.
// (JAX without x64 mode downcasts int64->int32; detect by checking that the
// odd 32-bit words of src are all zero, which holds iff the data is 8-byte
// little-endian values < 2^31. For int32 data these words are random node ids,
// so P(false positive) ~ (1/50000)^64 ~ 0.)
__global__ void k_init(const unsigned int* __restrict__ src_words) {
    int i = blockIdx.x * blockDim.x + threadIdx.x;
    if (i < N_NODES) g_deg[i] = 0;
    if (blockIdx.x == 0 && threadIdx.x == 0) {
        int all0 = 1;
        #pragma unroll
        for (int j = 1; j < 128; j += 2) all0 &= (src_words[j] == 0u);
        g_is64 = all0;
    }
}

// Kernel 2: in-degree histogram (int atomics, cheap).
__global__ void k_count(const void* __restrict__ dst) {
    int is64 = g_is64;
    int e = blockIdx.x * blockDim.x + threadIdx.x;
    if (e < N_EDGES) {
        int d = load_idx(dst, e, is64);
        atomicAdd(&g_deg[d], 1);
    }
}

// Kernel 3: single-block exclusive scan over degrees -> CSR offsets + cursors,
// plus per-node 1/sqrt(deg).
__global__ void k_scan() {
    const int C = (N_NODES + 1023) / 1024;  // 49 elems per thread
    int t = threadIdx.x;
    int base = t * C;
    int sum = 0;
    for (int i = 0; i < C; i++) {
        int idx = base + i;
        if (idx < N_NODES) sum += g_deg[idx];
    }
    __shared__ int part[1024];
    part[t] = sum;
    __syncthreads();
    // Hillis-Steele inclusive scan
    for (int ofs = 1; ofs < 1024; ofs <<= 1) {
        int v = (t >= ofs) ? part[t - ofs] : 0;
        __syncthreads();
        part[t] += v;
        __syncthreads();
    }
    int run = part[t] - sum;  // exclusive prefix for this chunk
    for (int i = 0; i < C; i++) {
        int idx = base + i;
        if (idx < N_NODES) {
            int d = g_deg[idx];
            g_off[idx] = run;
            g_cur[idx] = run;
            g_inv[idx] = rsqrtf((float)d);
            run += d;
            if (idx == N_NODES - 1) g_off[N_NODES] = run;
        }
    }
}

// Kernel 4: CSR fill via atomic cursors (int atomics only).
__global__ void k_fill(const void* __restrict__ src, const void* __restrict__ dst) {
    int is64 = g_is64;
    int e = blockIdx.x * blockDim.x + threadIdx.x;
    if (e < N_EDGES) {
        int d = load_idx(dst, e, is64);
        int s = load_idx(src, e, is64);
        int pos = atomicAdd(&g_cur[d], 1);
        g_csr_src[pos] = s;
    }
}

// Kernel 5: gather-based aggregation. One warp per destination node; each lane
// owns 4 contiguous feature columns (float4). No float atomics anywhere.
// agg[d] = inv[d] * sum_{s in neigh(d)} inv[s] * x[s]
__global__ void k_agg(const float* __restrict__ x) {
    int w    = (blockIdx.x * blockDim.x + threadIdx.x) >> 5;
    int lane = threadIdx.x & 31;
    if (w >= N_NODES) return;
    int beg = g_off[w];
    int end = g_off[w + 1];
    float4 acc = make_float4(0.f, 0.f, 0.f, 0.f);
    for (int e = beg; e < end; e++) {
        int   s = g_csr_src[e];            // uniform across warp (broadcast)
        float c = g_inv[s];                // uniform across warp
        float4 v = ((const float4*)(x + (size_t)s * D))[lane];
        acc.x += c * v.x;
        acc.y += c * v.y;
        acc.z += c * v.z;
        acc.w += c * v.w;
    }
    float invd = g_inv[w];
    acc.x *= invd; acc.y *= invd; acc.z *= invd; acc.w *= invd;
    ((float4*)(g_agg + (size_t)w * D))[lane] = acc;
}

// Kernel 6: out = agg @ W + deg * b.
// 32 rows per block, 256 threads: thread (tr,tc) computes rows tr*4..tr*4+3,
// cols tc*4..tc*4+3. A tile staged in shared (16 KB); W rows stream through L1
// (64 KB total, shared across all 8 warps -> hot in L1).
#define GR 32
__global__ void k_gemm(const float* __restrict__ W, const float* __restrict__ b,
                       float* __restrict__ out) {
    __shared__ float As[GR * D];
    int row0 = blockIdx.x * GR;
    int t = threadIdx.x;

    // cooperative load of the 32x128 A tile (1024 float4s / 256 threads)
    for (int i = t; i < GR * (D / 4); i += 256) {
        int r = i >> 5;        // row within tile
        int c4 = i & 31;       // float4 column
        int row = row0 + r;
        float4 v = (row < N_NODES)
                       ? ((const float4*)(g_agg + (size_t)row * D))[c4]
                       : make_float4(0.f, 0.f, 0.f, 0.f);
        ((float4*)As)[i] = v;
    }
    __syncthreads();

    int tc = t & 31;   // column group: cols 4*tc .. 4*tc+3
    int tr = t >> 5;   // row group:    rows 4*tr .. 4*tr+3 (within tile)

    float4 acc0 = make_float4(0.f, 0.f, 0.f, 0.f);
    float4 acc1 = make_float4(0.f, 0.f, 0.f, 0.f);
    float4 acc2 = make_float4(0.f, 0.f, 0.f, 0.f);
    float4 acc3 = make_float4(0.f, 0.f, 0.f, 0.f);

    #pragma unroll 8
    for (int k = 0; k < D; k++) {
        float4 w = ((const float4*)(W + (size_t)k * D))[tc];
        float a0 = As[(tr * 4 + 0) * D + k];
        float a1 = As[(tr * 4 + 1) * D + k];
        float a2 = As[(tr * 4 + 2) * D + k];
        float a3 = As[(tr * 4 + 3) * D + k];
        acc0.x += a0 * w.x; acc0.y += a0 * w.y; acc0.z += a0 * w.z; acc0.w += a0 * w.w;
        acc1.x += a1 * w.x; acc1.y += a1 * w.y; acc1.z += a1 * w.z; acc1.w += a1 * w.w;
        acc2.x += a2 * w.x; acc2.y += a2 * w.y; acc2.z += a2 * w.z; acc2.w += a2 * w.w;
        acc3.x += a3 * w.x; acc3.y += a3 * w.y; acc3.z += a3 * w.z; acc3.w += a3 * w.w;
    }

    float4 bv = ((const float4*)b)[tc];
    float4 accs[4] = {acc0, acc1, acc2, acc3};
    #pragma unroll
    for (int r = 0; r < 4; r++) {
        int row = row0 + tr * 4 + r;
        if (row < N_NODES) {
            float dg = (float)g_deg[row];
            float4 o;
            o.x = accs[r].x + dg * bv.x;
            o.y = accs[r].y + dg * bv.y;
            o.z = accs[r].z + dg * bv.z;
            o.w = accs[r].w + dg * bv.w;
            ((float4*)(out + (size_t)row * D))[tc] = o;
        }
    }
}

extern "C" void kernel_launch(void* const* d_in, const int* in_sizes, int n_in,
                              void* d_out, int out_size) {
    const float* x   = (const float*)d_in[0];
    const void*  src = d_in[1];
    const void*  dst = d_in[2];
    const float* W   = (const float*)d_in[3];
    const float* b   = (const float*)d_in[4];
    float* out = (float*)d_out;

    (void)in_sizes; (void)n_in; (void)out_size;

    k_init<<<(N_NODES + 255) / 256, 256>>>((const unsigned int*)src);
    k_count<<<(N_EDGES + 255) / 256, 256>>>(dst);
    k_scan<<<1, 1024>>>();
    k_fill<<<(N_EDGES + 255) / 256, 256>>>(src, dst);
    k_agg<<<(N_NODES * 32 + 255) / 256, 256>>>(x);
    k_gemm<<<(N_NODES + GR - 1) / GR, 256>>>(W, b, out);
}

// round 3
// speedup vs baseline: 1.0128x; 1.0128x over previous
#include <cuda_runtime.h>

#define N_NODES 50000
#define N_EDGES 600000
#define D 128

// ---- scratch (device globals: no allocation allowed) ----
__device__ int   g_deg[N_NODES];
__device__ int   g_off[N_NODES + 1];
__device__ int   g_cur[N_NODES];
__device__ float g_inv[N_NODES];
__device__ int   g_csr_src[N_EDGES];
__device__ float g_agg[(size_t)N_NODES * D];
__device__ int   g_is64;

__device__ __forceinline__ int load_idx(const void* p, int e, int is64) {
    if (is64) return (int)((const long long*)p)[e];
    return ((const int*)p)[e];
}

// Kernel 1: zero degree array + detect whether index arrays are int64 or int32.
// (JAX without x64 mode downcasts int64->int32; detect by checking that the
// odd 32-bit words of src are all zero, which holds iff the data is 8-byte
// little-endian values < 2^31. For int32 data these words are random node ids,
// so P(false positive) ~ (1/50000)^64 ~ 0.)
__global__ void k_init(const unsigned int* __restrict__ src_words) {
    int i = blockIdx.x * blockDim.x + threadIdx.x;
    if (i < N_NODES) g_deg[i] = 0;
    if (blockIdx.x == 0 && threadIdx.x == 0) {
        int all0 = 1;
        #pragma unroll
        for (int j = 1; j < 128; j += 2) all0 &= (src_words[j] == 0u);
        g_is64 = all0;
    }
}

// Kernel 2: in-degree histogram (int atomics, cheap).
__global__ void k_count(const void* __restrict__ dst) {
    int is64 = g_is64;
    int e = blockIdx.x * blockDim.x + threadIdx.x;
    if (e < N_EDGES) {
        int d = load_idx(dst, e, is64);
        atomicAdd(&g_deg[d], 1);
    }
}

// Kernel 3: single-block exclusive scan over degrees -> CSR offsets + cursors,
// plus per-node 1/sqrt(deg).
__global__ void k_scan() {
    const int C = (N_NODES + 1023) / 1024;  // 49 elems per thread
    int t = threadIdx.x;
    int base = t * C;
    int sum = 0;
    for (int i = 0; i < C; i++) {
        int idx = base + i;
        if (idx < N_NODES) sum += g_deg[idx];
    }
    __shared__ int part[1024];
    part[t] = sum;
    __syncthreads();
    // Hillis-Steele inclusive scan
    for (int ofs = 1; ofs < 1024; ofs <<= 1) {
        int v = (t >= ofs) ? part[t - ofs] : 0;
        __syncthreads();
        part[t] += v;
        __syncthreads();
    }
    int run = part[t] - sum;  // exclusive prefix for this chunk
    for (int i = 0; i < C; i++) {
        int idx = base + i;
        if (idx < N_NODES) {
            int d = g_deg[idx];
            g_off[idx] = run;
            g_cur[idx] = run;
            g_inv[idx] = rsqrtf((float)d);
            run += d;
            if (idx == N_NODES - 1) g_off[N_NODES] = run;
        }
    }
}

// Kernel 4: CSR fill via atomic cursors (int atomics only).
__global__ void k_fill(const void* __restrict__ src, const void* __restrict__ dst) {
    int is64 = g_is64;
    int e = blockIdx.x * blockDim.x + threadIdx.x;
    if (e < N_EDGES) {
        int d = load_idx(dst, e, is64);
        int s = load_idx(src, e, is64);
        int pos = atomicAdd(&g_cur[d], 1);
        g_csr_src[pos] = s;
    }
}

// Kernel 5: gather-based aggregation. One warp per destination node; each lane
// owns 4 contiguous feature columns (float4). No float atomics anywhere.
// agg[d] = inv[d] * sum_{s in neigh(d)} inv[s] * x[s]
__global__ void k_agg(const float* __restrict__ x) {
    int w    = (blockIdx.x * blockDim.x + threadIdx.x) >> 5;
    int lane = threadIdx.x & 31;
    if (w >= N_NODES) return;
    int beg = g_off[w];
    int end = g_off[w + 1];
    float4 acc = make_float4(0.f, 0.f, 0.f, 0.f);
    for (int e = beg; e < end; e++) {
        int   s = g_csr_src[e];            // uniform across warp (broadcast)
        float c = g_inv[s];                // uniform across warp
        float4 v = ((const float4*)(x + (size_t)s * D))[lane];
        acc.x += c * v.x;
        acc.y += c * v.y;
        acc.z += c * v.z;
        acc.w += c * v.w;
    }
    float invd = g_inv[w];
    acc.x *= invd; acc.y *= invd; acc.z *= invd; acc.w *= invd;
    ((float4*)(g_agg + (size_t)w * D))[lane] = acc;
}

// Kernel 6: out = agg @ W + deg * b.
// 32 rows per block, 256 threads: thread (tr,tc) computes rows tr*4..tr*4+3,
// cols tc*4..tc*4+3. A tile staged in shared (16 KB); W rows stream through L1
// (64 KB total, shared across all 8 warps -> hot in L1).
#define GR 32
__global__ void k_gemm(const float* __restrict__ W, const float* __restrict__ b,
                       float* __restrict__ out) {
    __shared__ float As[GR * D];
    int row0 = blockIdx.x * GR;
    int t = threadIdx.x;

    // cooperative load of the 32x128 A tile (1024 float4s / 256 threads)
    for (int i = t; i < GR * (D / 4); i += 256) {
        int r = i >> 5;        // row within tile
        int c4 = i & 31;       // float4 column
        int row = row0 + r;
        float4 v = (row < N_NODES)
                       ? ((const float4*)(g_agg + (size_t)row * D))[c4]
                       : make_float4(0.f, 0.f, 0.f, 0.f);
        ((float4*)As)[i] = v;
    }
    __syncthreads();

    int tc = t & 31;   // column group: cols 4*tc .. 4*tc+3
    int tr = t >> 5;   // row group:    rows 4*tr .. 4*tr+3 (within tile)

    float4 acc0 = make_float4(0.f, 0.f, 0.f, 0.f);
    float4 acc1 = make_float4(0.f, 0.f, 0.f, 0.f);
    float4 acc2 = make_float4(0.f, 0.f, 0.f, 0.f);
    float4 acc3 = make_float4(0.f, 0.f, 0.f, 0.f);

    #pragma unroll 8
    for (int k = 0; k < D; k++) {
        float4 w = ((const float4*)(W + (size_t)k * D))[tc];
        float a0 = As[(tr * 4 + 0) * D + k];
        float a1 = As[(tr * 4 + 1) * D + k];
        float a2 = As[(tr * 4 + 2) * D + k];
        float a3 = As[(tr * 4 + 3) * D + k];
        acc0.x += a0 * w.x; acc0.y += a0 * w.y; acc0.z += a0 * w.z; acc0.w += a0 * w.w;
        acc1.x += a1 * w.x; acc1.y += a1 * w.y; acc1.z += a1 * w.z; acc1.w += a1 * w.w;
        acc2.x += a2 * w.x; acc2.y += a2 * w.y; acc2.z += a2 * w.z; acc2.w += a2 * w.w;
        acc3.x += a3 * w.x; acc3.y += a3 * w.y; acc3.z += a3 * w.z; acc3.w += a3 * w.w;
    }

    float4 bv = ((const float4*)b)[tc];
    float4 accs[4] = {acc0, acc1, acc2, acc3};
    #pragma unroll
    for (int r = 0; r < 4; r++) {
        int row = row0 + tr * 4 + r;
        if (row < N_NODES) {
            float dg = (float)g_deg[row];
            float4 o;
            o.x = accs[r].x + dg * bv.x;
            o.y = accs[r].y + dg * bv.y;
            o.z = accs[r].z + dg * bv.z;
            o.w = accs[r].w + dg * bv.w;
            ((float4*)(out + (size_t)row * D))[tc] = o;
        }
    }
}

extern "C" void kernel_launch(void* const* d_in, const int* in_sizes, int n_in,
                              void* d_out, int out_size) {
    const float* x   = (const float*)d_in[0];
    const void*  src = d_in[1];
    const void*  dst = d_in[2];
    const float* W   = (const float*)d_in[3];
    const float* b   = (const float*)d_in[4];
    float* out = (float*)d_out;

    (void)in_sizes; (void)n_in; (void)out_size;

    k_init<<<(N_NODES + 255) / 256, 256>>>((const unsigned int*)src);
    k_count<<<(N_EDGES + 255) / 256, 256>>>(dst);
    k_scan<<<1, 1024>>>();
    k_fill<<<(N_EDGES + 255) / 256, 256>>>(src, dst);
    k_agg<<<(N_NODES * 32 + 255) / 256, 256>>>(x);
    k_gemm<<<(N_NODES + GR - 1) / GR, 256>>>(W, b, out);
}